// round 14
// baseline (speedup 1.0000x reference)
#include <cuda_runtime.h>
#include <cuda_fp16.h>
#include <math.h>
#include <stdint.h>

#define B_ 8192
#define H_ 896
#define S_ 448
#define Q_ 256

// ---------------- scratch (allocation-free __device__ globals) ----------------
__device__ __half g_R[3ull * B_ * H_];       // R_u | R_r | R_e (fp16)
__device__ __half g_Ah[(size_t)B_ * H_];     // prev_hidden fp16
__device__ __half g_Hh[(size_t)B_ * H_];     // hidden fp16
__device__ __half g_Th[2ull * B_ * S_];      // relu(t1)|relu(t2) fp16
#define WSZ (3 * H_ * H_ + 2 * S_ * S_ + 2 * Q_ * S_)
__device__ __half g_Wh[WSZ];

#define OFF_WR  0
#define OFF_WO1 (3 * H_ * H_)
#define OFF_WO2 (3 * H_ * H_ + 2 * S_ * S_)

// ---------------- PTX helpers (base sm_80+ features only) ----------------
__device__ __forceinline__ uint32_t s2u(const void* p) {
    return (uint32_t)__cvta_generic_to_shared(p);
}
__device__ __forceinline__ void cp_async16(uint32_t dst, const void* src, uint32_t bytes) {
    asm volatile("cp.async.cg.shared.global [%0], [%1], 16, %2;"
                 :: "r"(dst), "l"(src), "r"(bytes) : "memory");
}
__device__ __forceinline__ void cp_commit() {
    asm volatile("cp.async.commit_group;" ::: "memory");
}
template<int NN>
__device__ __forceinline__ void cp_wait() {
    asm volatile("cp.async.wait_group %0;" :: "n"(NN) : "memory");
}
__device__ __forceinline__ void ldm_x4(uint32_t* r, uint32_t addr) {
    asm volatile("ldmatrix.sync.aligned.m8n8.x4.shared.b16 {%0,%1,%2,%3}, [%4];"
                 : "=r"(r[0]), "=r"(r[1]), "=r"(r[2]), "=r"(r[3]) : "r"(addr));
}
__device__ __forceinline__ void mma_fp16(float* d, const uint32_t* a, uint32_t b0, uint32_t b1) {
    asm volatile("mma.sync.aligned.m16n8k16.row.col.f32.f16.f16.f32 "
                 "{%0,%1,%2,%3}, {%4,%5,%6,%7}, {%8,%9}, {%0,%1,%2,%3};"
                 : "+f"(d[0]), "+f"(d[1]), "+f"(d[2]), "+f"(d[3])
                 : "r"(a[0]), "r"(a[1]), "r"(a[2]), "r"(a[3]), "r"(b0), "r"(b1));
}
__device__ __forceinline__ float ftanh(float x) {
    float y; asm("tanh.approx.f32 %0, %1;" : "=f"(y) : "f"(x)); return y;
}
__device__ __forceinline__ float fsigm(float x) {
    return 1.0f / (1.0f + __expf(-x));
}

// ---------------- GEMM: C[M=8192,N] = A[M,K] @ W[N,K]^T (fp16 in, fp32 acc) ---
// CTA tile 256(m) x 128(n) x 32(k); 512 threads, 16 warps as 4m x 4n ->
// 64x32 warp tiles: per chunk smem ~940 cyc < tensor 1024 cyc (tensor-bound),
// 16 warps/SM at 1 CTA/SM (<=128 regs via launch_bounds).
// PERSISTENT: grid.x CTAs loop over all (m,n) tiles; post-k-loop barrier keeps
// next tile's stage writes from racing laggard readers; cp.async groups drain
// at each tile's last chunk (wait<0>).
// Pipeline: NST=6, LOOK=4 (obeys LOOK <= NST-2: loads issue BEFORE the chunk
// barrier, so write slot (c+LOOK)%NST must differ from (c-1)%NST).
// stage: A(16K) | W(8K) = 24KB.
// EPI: 0 = fp16 store, 1 = +bias fp32 store, 2 = relu(+bias) -> fp16 store
// grid.z batches two independent GEMMs (zA/zW/zC element strides, bias0/bias1).
#define SBYTES 24576
#define NST 6
#define GLOOK 4
#define SMEM_TOTAL (NST * SBYTES)   // 147456
#define NSM_ 148

template<int EPI, bool SPLITC>
__global__ __launch_bounds__(512, 1)
void gemm_mma(const __half* __restrict__ Ah_, int lda,
              const __half* __restrict__ Wh_,
              int N, int K, const float* __restrict__ bias0, const float* __restrict__ bias1,
              float* __restrict__ Cf, __half* __restrict__ Ch, int ldc,
              int zA, int zW, int zC)
{
    extern __shared__ char smem[];
    const int z = blockIdx.z;
    const __half* Ah = Ah_ + (size_t)z * zA;
    const __half* Wh = Wh_ + (size_t)z * zW;
    const float* bias = z ? bias1 : bias0;

    const int t    = threadIdx.x;
    const int lane = t & 31;
    const int wid  = t >> 5;
    const int wm = (wid & 3) * 64;   // 4 warp-groups along m
    const int wn = (wid >> 2) * 32;  // 4 warp-groups along n
    const uint32_t sb0 = s2u(smem);
    const int nch = K / 32;
    const int tilesX = (N + 127) >> 7;
    const int ntiles = tilesX * (B_ / 256);

    const int arow = (lane & 7) + ((lane >> 3) & 1) * 8;
    const int asel = (lane >> 4) & 1;
    const int brow = (lane & 7) + ((lane >> 4) & 1) * 8;
    const int bsel = (lane >> 3) & 1;
    const int gid = lane >> 2;
    const int cp2 = (lane & 3) * 2;

    for (int tile = blockIdx.x; tile < ntiles; tile += gridDim.x) {
        const int ty = tile / tilesX;
        const int m0 = ty * 256;
        const int n0 = (tile - ty * tilesX) * 128;
        const int tile_n = SPLITC ? 128 : min(128, N - n0);

        float acc[4][4][4];
#pragma unroll
        for (int a = 0; a < 4; a++)
#pragma unroll
            for (int b = 0; b < 4; b++)
#pragma unroll
                for (int d = 0; d < 4; d++) acc[a][b][d] = 0.f;

        auto load_stage = [&](int c, int st) {
            const int k0 = c * 32;
            const uint32_t sb = sb0 + st * SBYTES;
#pragma unroll
            for (int i = 0; i < 2; ++i) {              // A: 256 rows x 4 chunks
                const int within = t + i * 512;        // 0..1023
                const int row    = within >> 2;        // 0..255
                const int ch     = within & 3;
                const uint32_t dst = sb + row * 64 + ((ch ^ ((row >> 1) & 3)) * 16);
                cp_async16(dst, Ah + (size_t)(m0 + row) * lda + k0 + ch * 8, 16);
            }
            {                                          // W: 128 rows x 4 chunks
                const int row = t >> 2;                // 0..127
                const int ch  = t & 3;
                const uint32_t dst = sb + 16384 + row * 64 + ((ch ^ ((row >> 1) & 3)) * 16);
                const int r = (row < tile_n) ? row : (tile_n - 1);
                cp_async16(dst, Wh + (size_t)(n0 + r) * K + k0 + ch * 8,
                           (row < tile_n) ? 16u : 0u);
            }
            cp_commit();
        };

#pragma unroll
        for (int s = 0; s < GLOOK; ++s)
            load_stage(s, s);

        for (int c = 0; c < nch; ++c) {
            if (c + GLOOK < nch) { load_stage(c + GLOOK, (c + GLOOK) % NST); cp_wait<GLOOK>(); }
            else {
                const int rem = nch - 1 - c;    // 0..GLOOK-1
                if (rem >= 3)      cp_wait<3>();
                else if (rem == 2) cp_wait<2>();
                else if (rem == 1) cp_wait<1>();
                else               cp_wait<0>();
            }
            __syncthreads();
            const uint32_t sb = sb0 + (c % NST) * SBYTES;
#pragma unroll
            for (int ks = 0; ks < 2; ++ks) {
                uint32_t ahf[4][4];
                const int ach = ks * 2 + asel;
#pragma unroll
                for (int mt = 0; mt < 4; ++mt) {
                    const int row = wm + mt * 16 + arow;
                    const uint32_t ad = sb + row * 64 + ((ach ^ ((row >> 1) & 3)) * 16);
                    ldm_x4(ahf[mt], ad);
                }
                uint32_t bhf[2][4];
                const int bch = ks * 2 + bsel;
#pragma unroll
                for (int p = 0; p < 2; ++p) {
                    const int nrow = wn + p * 16 + brow;
                    const uint32_t bd = sb + 16384 + nrow * 64 +
                                        ((bch ^ ((nrow >> 1) & 3)) * 16);
                    ldm_x4(bhf[p], bd);
                }
#pragma unroll
                for (int mt = 0; mt < 4; ++mt)
#pragma unroll
                    for (int q = 0; q < 4; ++q)
                        mma_fp16(acc[mt][q], ahf[mt],
                                 bhf[q >> 1][(q & 1) * 2], bhf[q >> 1][(q & 1) * 2 + 1]);
            }
        }

        // all warps done reading smem before next tile's stage writes
        __syncthreads();

        // ---- epilogue
        float*  Cf2 = Cf + (size_t)z * zC;
        __half* Ch2 = Ch + (size_t)z * zC;
        int ncol0 = n0;
        if (SPLITC) {
            const int g = n0 / H_;
            Ch2 = Ch + (size_t)g * B_ * H_;
            ncol0 = n0 - g * H_;
        }
#pragma unroll
        for (int mt = 0; mt < 4; ++mt) {
            const int r0 = m0 + wm + mt * 16 + gid;
#pragma unroll
            for (int nt = 0; nt < 4; ++nt) {
                const int cloc = wn + nt * 8 + cp2;
                if (SPLITC || n0 + cloc < N) {
                    const int col = ncol0 + cloc;
                    float x0 = acc[mt][nt][0], x1 = acc[mt][nt][1];
                    float x2 = acc[mt][nt][2], x3 = acc[mt][nt][3];
                    if (EPI >= 1) {
                        const float bb0 = bias[col], bb1 = bias[col + 1];
                        x0 += bb0; x1 += bb1; x2 += bb0; x3 += bb1;
                    }
                    if (EPI == 2) {
                        x0 = fmaxf(x0, 0.f); x1 = fmaxf(x1, 0.f);
                        x2 = fmaxf(x2, 0.f); x3 = fmaxf(x3, 0.f);
                    }
                    if (EPI == 1) {
                        *(float2*)(Cf2 + (size_t)r0 * ldc + col)       = make_float2(x0, x1);
                        *(float2*)(Cf2 + (size_t)(r0 + 8) * ldc + col) = make_float2(x2, x3);
                    } else {
                        *(__half2*)(Ch2 + (size_t)r0 * ldc + col) =
                            __halves2half2(__float2half(x0), __float2half(x1));
                        *(__half2*)(Ch2 + (size_t)(r0 + 8) * ldc + col) =
                            __halves2half2(__float2half(x2), __float2half(x3));
                    }
                }
            }
        }
    }
}

// ---------------- merged fp32 -> fp16 convert (all operands, one launch) ------
__global__ void cvtAll_kernel(const float4* __restrict__ ph,
                              const float4* __restrict__ wru, const float4* __restrict__ wrr,
                              const float4* __restrict__ wre,
                              const float4* __restrict__ wo1, const float4* __restrict__ wo3,
                              const float4* __restrict__ wo2, const float4* __restrict__ wo4,
                              __half* __restrict__ Ah, __half* __restrict__ Wh)
{
    const int nA = B_ * H_ / 4;
    const int nH = H_ * H_ / 4;
    const int nS = S_ * S_ / 4;
    const int nQ = Q_ * S_ / 4;
    int i = blockIdx.x * blockDim.x + threadIdx.x;

    float4 x;
    __half* dst;
    int di;
    if (i < nA) {
        x = ph[i]; dst = Ah; di = i;
    } else {
        int j = i - nA;
        dst = Wh; di = j;
        if      (j < nH)              x = wru[j];
        else if (j < 2 * nH)          x = wrr[j - nH];
        else if (j < 3 * nH)          x = wre[j - 2 * nH];
        else if (j < 3 * nH + nS)     x = wo1[j - 3 * nH];
        else if (j < 3 * nH + 2 * nS) x = wo3[j - 3 * nH - nS];
        else if (j < 3 * nH + 2 * nS + nQ)     x = wo2[j - 3 * nH - 2 * nS];
        else if (j < 3 * nH + 2 * nS + 2 * nQ) x = wo4[j - 3 * nH - 2 * nS - nQ];
        else return;
    }
    __half h[4];
    h[0] = __float2half(x.x); h[1] = __float2half(x.y);
    h[2] = __float2half(x.z); h[3] = __float2half(x.w);
    *(uint2*)(dst + 4 * (size_t)di) = *(uint2*)h;
}

// ---------------- fused gate (vec x4, fast math, fp16 R input) ----------------
__global__ void gate_kernel(const float* __restrict__ prev_y,
                            const float* __restrict__ prev_hidden,
                            const float* __restrict__ coarse,
                            const float* __restrict__ W_Ic,
                            const float* __restrict__ W_If,
                            const float* __restrict__ bias_u,
                            const float* __restrict__ bias_r,
                            const float* __restrict__ bias_e,
                            const __half* __restrict__ Rbuf,
                            float* __restrict__ hidden_out,
                            __half* __restrict__ hid_h)
{
    const int HV = H_ / 4;
    int v = blockIdx.x * blockDim.x + threadIdx.x;
    if (v >= B_ * HV) return;
    int b = v / HV;
    int j = (v - b * HV) * 4;
    size_t idx = (size_t)b * H_ + j;
    const size_t NBH = (size_t)B_ * H_;

    float py0 = prev_y[2 * b], py1 = prev_y[2 * b + 1];

    __half Ru2[4], Rr2[4], Re2[4];
    *(uint2*)Ru2 = *(const uint2*)(Rbuf + idx);
    *(uint2*)Rr2 = *(const uint2*)(Rbuf + NBH + idx);
    *(uint2*)Re2 = *(const uint2*)(Rbuf + 2 * NBH + idx);
    float4 ph4 = *(const float4*)(prev_hidden + idx);
    const float* ph = (const float*)&ph4;

    float h[4];
    if (j < S_) {
#pragma unroll
        for (int q = 0; q < 4; ++q) {
            int jj = j + q;
            float Iu = py0 * W_Ic[jj * 2] + py1 * W_Ic[jj * 2 + 1];
            float Ir = py0 * W_Ic[(S_ + jj) * 2] + py1 * W_Ic[(S_ + jj) * 2 + 1];
            float Ie = py0 * W_Ic[(2 * S_ + jj) * 2] + py1 * W_Ic[(2 * S_ + jj) * 2 + 1];
            float u = fsigm(__half2float(Ru2[q]) + Iu + bias_u[jj]);
            float r = fsigm(__half2float(Rr2[q]) + Ir + bias_r[jj]);
            float e = ftanh(r * __half2float(Re2[q]) + Ie + bias_e[jj]);
            h[q] = u * ph[q] + (1.f - u) * e;
        }
    } else {
        float cc = coarse[b];
#pragma unroll
        for (int q = 0; q < 4; ++q) {
            int jj = j + q;
            int jf = jj - S_;
            float Iu = py0 * W_If[jf * 3] + py1 * W_If[jf * 3 + 1] + cc * W_If[jf * 3 + 2];
            float Ir = py0 * W_If[(S_ + jf) * 3] + py1 * W_If[(S_ + jf) * 3 + 1] + cc * W_If[(S_ + jf) * 3 + 2];
            float Ie = py0 * W_If[(2 * S_ + jf) * 3] + py1 * W_If[(2 * S_ + jf) * 3 + 1] + cc * W_If[(2 * S_ + jf) * 3 + 2];
            float u = fsigm(__half2float(Ru2[q]) + Iu + bias_u[jj]);
            float r = fsigm(__half2float(Rr2[q]) + Ir + bias_r[jj]);
            float e = ftanh(r * __half2float(Re2[q]) + Ie + bias_e[jj]);
            h[q] = u * ph[q] + (1.f - u) * e;
        }
    }

    *(float4*)(hidden_out + idx) = make_float4(h[0], h[1], h[2], h[3]);

    __half hh[4];
#pragma unroll
    for (int q = 0; q < 4; ++q) hh[q] = __float2half(h[q]);
    *(uint2*)(hid_h + idx) = *(uint2*)hh;
}

// ---------------- launch ----------------
extern "C" void kernel_launch(void* const* d_in, const int* in_sizes, int n_in,
                              void* d_out, int out_size)
{
    const float* prev_y      = (const float*)d_in[0];
    const float* prev_hidden = (const float*)d_in[1];
    const float* coarse      = (const float*)d_in[2];
    const float* W_Ru        = (const float*)d_in[3];
    const float* W_Rr        = (const float*)d_in[4];
    const float* W_Re        = (const float*)d_in[5];
    const float* W_Ic        = (const float*)d_in[6];
    const float* W_If        = (const float*)d_in[7];
    const float* W_O1        = (const float*)d_in[8];
    const float* b_O1        = (const float*)d_in[9];
    const float* W_O2        = (const float*)d_in[10];
    const float* b_O2        = (const float*)d_in[11];
    const float* W_O3        = (const float*)d_in[12];
    const float* b_O3        = (const float*)d_in[13];
    const float* W_O4        = (const float*)d_in[14];
    const float* b_O4        = (const float*)d_in[15];
    const float* bias_u      = (const float*)d_in[16];
    const float* bias_r      = (const float*)d_in[17];
    const float* bias_e      = (const float*)d_in[18];

    float* out        = (float*)d_out;
    float* out_coarse = out;
    float* hidden     = out + 2 * (size_t)B_ * Q_;

    __half *Rbuf, *Ah, *Hh, *Th, *Wh;
    cudaGetSymbolAddress((void**)&Rbuf, g_R);
    cudaGetSymbolAddress((void**)&Ah, g_Ah);
    cudaGetSymbolAddress((void**)&Hh, g_Hh);
    cudaGetSymbolAddress((void**)&Th, g_Th);
    cudaGetSymbolAddress((void**)&Wh, g_Wh);

    cudaFuncSetAttribute(gemm_mma<0, true>,  cudaFuncAttributeMaxDynamicSharedMemorySize, SMEM_TOTAL);
    cudaFuncSetAttribute(gemm_mma<2, false>, cudaFuncAttributeMaxDynamicSharedMemorySize, SMEM_TOTAL);
    cudaFuncSetAttribute(gemm_mma<1, false>, cudaFuncAttributeMaxDynamicSharedMemorySize, SMEM_TOTAL);

    const int NBS = B_ * S_;
    const int NCVT = B_ * H_ / 4 + WSZ / 4;

    // merged converts (1 launch)
    cvtAll_kernel<<<(NCVT + 255) / 256, 256>>>(
        (const float4*)prev_hidden,
        (const float4*)W_Ru, (const float4*)W_Rr, (const float4*)W_Re,
        (const float4*)W_O1, (const float4*)W_O3, (const float4*)W_O2, (const float4*)W_O4,
        Ah, Wh);

    // fused recurrent projections -> R (fp16), N = 3*H = 2688, persistent grid
    {
        const int ntiles = (3 * H_ / 128) * (B_ / 256);   // 21*32 = 672
        dim3 g1(NSM_ < ntiles ? NSM_ : ntiles, 1, 1);
        gemm_mma<0, true><<<g1, 512, SMEM_TOTAL>>>(Ah, H_, Wh + OFF_WR,
                                                   3 * H_, H_, nullptr, nullptr,
                                                   nullptr, Rbuf, H_, 0, 0, 0);
    }

    // fused gates -> hidden (fp32 to d_out) + fp16 copy
    gate_kernel<<<(B_ * (H_ / 4) + 255) / 256, 256>>>(prev_y, prev_hidden, coarse, W_Ic, W_If,
                                                      bias_u, bias_r, bias_e, Rbuf, hidden, Hh);

    // relu(h_half @ W^T + b) -> fp16 scratch; z batches O1 / O3
    {
        const int ntiles = ((S_ + 127) / 128) * (B_ / 256);   // 4*32 = 128
        dim3 g2(NSM_ < ntiles ? NSM_ : ntiles, 1, 2);
        gemm_mma<2, false><<<g2, 512, SMEM_TOTAL>>>(Hh, H_, Wh + OFF_WO1,
                                                    S_, S_, b_O1, b_O3,
                                                    nullptr, Th, S_,
                                                    S_, S_ * S_, NBS);
    }

    // logits -> d_out; z batches O2 / O4
    {
        const int ntiles = (Q_ / 128) * (B_ / 256);   // 2*32 = 64
        dim3 g3(NSM_ < ntiles ? NSM_ : ntiles, 1, 2);
        gemm_mma<1, false><<<g3, 512, SMEM_TOTAL>>>(Th, S_, Wh + OFF_WO2,
                                                    Q_, S_, b_O2, b_O4,
                                                    out_coarse, nullptr, Q_,
                                                    NBS, Q_ * S_, B_ * Q_);
    }
}

// round 16
// speedup vs baseline: 1.1490x; 1.1490x over previous
#include <cuda_runtime.h>
#include <cuda_fp16.h>
#include <math.h>
#include <stdint.h>

#define B_ 8192
#define H_ 896
#define S_ 448
#define Q_ 256

// ---------------- scratch (allocation-free __device__ globals) ----------------
__device__ __half g_R[3ull * B_ * H_];       // R_u | R_r | R_e (fp16)
__device__ __half g_Ah[(size_t)B_ * H_];     // prev_hidden fp16
__device__ __half g_Hh[(size_t)B_ * H_];     // hidden fp16
__device__ __half g_Th[2ull * B_ * S_];      // relu(t1)|relu(t2) fp16
#define WSZ (3 * H_ * H_ + 2 * S_ * S_ + 2 * Q_ * S_)
__device__ __half g_Wh[WSZ];

#define OFF_WR  0
#define OFF_WO1 (3 * H_ * H_)
#define OFF_WO2 (3 * H_ * H_ + 2 * S_ * S_)

// ---------------- PTX helpers (base sm_80+ features only) ----------------
__device__ __forceinline__ uint32_t s2u(const void* p) {
    return (uint32_t)__cvta_generic_to_shared(p);
}
__device__ __forceinline__ void cp_async16(uint32_t dst, const void* src, uint32_t bytes) {
    asm volatile("cp.async.cg.shared.global [%0], [%1], 16, %2;"
                 :: "r"(dst), "l"(src), "r"(bytes) : "memory");
}
__device__ __forceinline__ void cp_commit() {
    asm volatile("cp.async.commit_group;" ::: "memory");
}
template<int NN>
__device__ __forceinline__ void cp_wait() {
    asm volatile("cp.async.wait_group %0;" :: "n"(NN) : "memory");
}
__device__ __forceinline__ void ldm_x4(uint32_t* r, uint32_t addr) {
    asm volatile("ldmatrix.sync.aligned.m8n8.x4.shared.b16 {%0,%1,%2,%3}, [%4];"
                 : "=r"(r[0]), "=r"(r[1]), "=r"(r[2]), "=r"(r[3]) : "r"(addr));
}
__device__ __forceinline__ void mma_fp16(float* d, const uint32_t* a, uint32_t b0, uint32_t b1) {
    asm volatile("mma.sync.aligned.m16n8k16.row.col.f32.f16.f16.f32 "
                 "{%0,%1,%2,%3}, {%4,%5,%6,%7}, {%8,%9}, {%0,%1,%2,%3};"
                 : "+f"(d[0]), "+f"(d[1]), "+f"(d[2]), "+f"(d[3])
                 : "r"(a[0]), "r"(a[1]), "r"(a[2]), "r"(a[3]), "r"(b0), "r"(b1));
}
__device__ __forceinline__ float ftanh(float x) {
    float y; asm("tanh.approx.f32 %0, %1;" : "=f"(y) : "f"(x)); return y;
}
__device__ __forceinline__ float fsigm(float x) {
    return 1.0f / (1.0f + __expf(-x));
}

// ---------------- GEMM: C[M,N] = A[M,K] @ W[N,K]^T (fp16 in, fp32 acc) --------
// R11-proven shape: CTA 128x128, 256 threads, 8 warps as 4m x 2n (32x64 warp
// tiles), 2 CTAs/SM. NEW: 64-k stages (A 16K | W 16K, SW128 on 128B rows) ->
// ONE barrier per 64 k instead of two (7 barriers/tile for K=896), halving
// barrier drain overhead. NST=3, LOOK=1; race rule holds mod 3: write slot
// (p+1)%3 != laggard-read slot (p-1)%3. LOOK=1 latency budget: per-stage
// compute wall ~2048 cyc (2 CTA/SM) >> L2 latency.
// EPI: 0 = fp16 store, 1 = +bias fp32 store, 2 = relu(+bias) -> fp16 store
// grid.z batches two independent GEMMs (zA/zW/zC element strides, bias0/bias1).
#define SBYTES 32768
#define NST 3
#define SMEM_TOTAL (NST * SBYTES)   // 98304

template<int EPI, bool SPLITC>
__global__ __launch_bounds__(256, 2)
void gemm_mma(const __half* __restrict__ Ah_, int lda,
              const __half* __restrict__ Wh_,
              int N, int K, const float* __restrict__ bias0, const float* __restrict__ bias1,
              float* __restrict__ Cf, __half* __restrict__ Ch, int ldc,
              int zA, int zW, int zC)
{
    extern __shared__ char smem[];
    const int z = blockIdx.z;
    const __half* Ah = Ah_ + (size_t)z * zA;
    const __half* Wh = Wh_ + (size_t)z * zW;
    const float* bias = z ? bias1 : bias0;

    const int t  = threadIdx.x;
    const int m0 = blockIdx.y * 128;
    const int n0 = blockIdx.x * 128;
    const int tile_n = SPLITC ? 128 : min(128, N - n0);
    const uint32_t sb0 = s2u(smem);
    const int lane = t & 31;
    const int wid  = t >> 5;
    const int wm = (wid & 3) * 32;
    const int wn = (wid >> 2) * 64;

    float acc[2][8][4];
#pragma unroll
    for (int a = 0; a < 2; a++)
#pragma unroll
        for (int b = 0; b < 8; b++)
#pragma unroll
            for (int d = 0; d < 4; d++) acc[a][b][d] = 0.f;

    const int npair = K / 64;

    auto load_stage = [&](int p, int st) {
        const int k0 = p * 64;
        const uint32_t sb = sb0 + st * SBYTES;
        // A: 128 rows x 8 chunks (16B) = 1024 ops, 4 per thread
#pragma unroll
        for (int i = 0; i < 4; ++i) {
            const int within = t + i * 256;        // 0..1023
            const int row    = within >> 3;        // 0..127
            const int ch     = within & 7;
            const uint32_t dst = sb + row * 128 + ((ch ^ (row & 7)) * 16);
            cp_async16(dst, Ah + (size_t)(m0 + row) * lda + k0 + ch * 8, 16);
        }
        // W: 128 rows x 8 chunks
#pragma unroll
        for (int i = 0; i < 4; ++i) {
            const int within = t + i * 256;
            const int row    = within >> 3;
            const int ch     = within & 7;
            const uint32_t dst = sb + 16384 + row * 128 + ((ch ^ (row & 7)) * 16);
            const int r = (row < tile_n) ? row : (tile_n - 1);
            cp_async16(dst, Wh + (size_t)(n0 + r) * K + k0 + ch * 8,
                       (row < tile_n) ? 16u : 0u);
        }
        cp_commit();
    };

    load_stage(0, 0);

    const int arow = (lane & 7) + ((lane >> 3) & 1) * 8;
    const int asel = (lane >> 4) & 1;
    const int brow = (lane & 7) + ((lane >> 4) & 1) * 8;
    const int bsel = (lane >> 3) & 1;

    for (int p = 0; p < npair; ++p) {
        if (p + 1 < npair) { load_stage(p + 1, (p + 1) % NST); cp_wait<1>(); }
        else               { cp_wait<0>(); }
        __syncthreads();
        const uint32_t sb = sb0 + (p % NST) * SBYTES;
#pragma unroll
        for (int ks = 0; ks < 4; ++ks) {
            uint32_t ahf[2][4];
            const int ach = ks * 2 + asel;
#pragma unroll
            for (int mt = 0; mt < 2; ++mt) {
                const int row = wm + mt * 16 + arow;
                const uint32_t ad = sb + row * 128 + ((ach ^ (row & 7)) * 16);
                ldm_x4(ahf[mt], ad);
            }
            const int bch = ks * 2 + bsel;
#pragma unroll
            for (int hb = 0; hb < 2; ++hb) {
                uint32_t bhf[2][4];
#pragma unroll
                for (int q = 0; q < 2; ++q) {
                    const int nrow = wn + hb * 32 + q * 16 + brow;
                    const uint32_t bd = sb + 16384 + nrow * 128 +
                                        ((bch ^ (nrow & 7)) * 16);
                    ldm_x4(bhf[q], bd);
                }
#pragma unroll
                for (int mt = 0; mt < 2; ++mt)
#pragma unroll
                    for (int q = 0; q < 4; ++q)
                        mma_fp16(acc[mt][hb * 4 + q], ahf[mt],
                                 bhf[q >> 1][(q & 1) * 2], bhf[q >> 1][(q & 1) * 2 + 1]);
            }
        }
    }

    // ---- epilogue
    float*  Cf2 = Cf + (size_t)z * zC;
    __half* Ch2 = Ch + (size_t)z * zC;
    int ncol0 = n0;
    if (SPLITC) {
        const int g = n0 / H_;
        Ch2 = Ch + (size_t)g * B_ * H_;
        ncol0 = n0 - g * H_;
    }
    const int gid = lane >> 2;
    const int cp2 = (lane & 3) * 2;
#pragma unroll
    for (int mt = 0; mt < 2; ++mt) {
        const int r0 = m0 + wm + mt * 16 + gid;
#pragma unroll
        for (int nt = 0; nt < 8; ++nt) {
            const int cloc = wn + nt * 8 + cp2;
            if (SPLITC || n0 + cloc < N) {
                const int col = ncol0 + cloc;
                float x0 = acc[mt][nt][0], x1 = acc[mt][nt][1];
                float x2 = acc[mt][nt][2], x3 = acc[mt][nt][3];
                if (EPI >= 1) {
                    const float bb0 = bias[col], bb1 = bias[col + 1];
                    x0 += bb0; x1 += bb1; x2 += bb0; x3 += bb1;
                }
                if (EPI == 2) {
                    x0 = fmaxf(x0, 0.f); x1 = fmaxf(x1, 0.f);
                    x2 = fmaxf(x2, 0.f); x3 = fmaxf(x3, 0.f);
                }
                if (EPI == 1) {
                    *(float2*)(Cf2 + (size_t)r0 * ldc + col)       = make_float2(x0, x1);
                    *(float2*)(Cf2 + (size_t)(r0 + 8) * ldc + col) = make_float2(x2, x3);
                } else {
                    *(__half2*)(Ch2 + (size_t)r0 * ldc + col) =
                        __halves2half2(__float2half(x0), __float2half(x1));
                    *(__half2*)(Ch2 + (size_t)(r0 + 8) * ldc + col) =
                        __halves2half2(__float2half(x2), __float2half(x3));
                }
            }
        }
    }
}

// ---------------- merged fp32 -> fp16 convert (all operands, one launch) ------
__global__ void cvtAll_kernel(const float4* __restrict__ ph,
                              const float4* __restrict__ wru, const float4* __restrict__ wrr,
                              const float4* __restrict__ wre,
                              const float4* __restrict__ wo1, const float4* __restrict__ wo3,
                              const float4* __restrict__ wo2, const float4* __restrict__ wo4,
                              __half* __restrict__ Ah, __half* __restrict__ Wh)
{
    const int nA = B_ * H_ / 4;
    const int nH = H_ * H_ / 4;
    const int nS = S_ * S_ / 4;
    const int nQ = Q_ * S_ / 4;
    int i = blockIdx.x * blockDim.x + threadIdx.x;

    float4 x;
    __half* dst;
    int di;
    if (i < nA) {
        x = ph[i]; dst = Ah; di = i;
    } else {
        int j = i - nA;
        dst = Wh; di = j;
        if      (j < nH)              x = wru[j];
        else if (j < 2 * nH)          x = wrr[j - nH];
        else if (j < 3 * nH)          x = wre[j - 2 * nH];
        else if (j < 3 * nH + nS)     x = wo1[j - 3 * nH];
        else if (j < 3 * nH + 2 * nS) x = wo3[j - 3 * nH - nS];
        else if (j < 3 * nH + 2 * nS + nQ)     x = wo2[j - 3 * nH - 2 * nS];
        else if (j < 3 * nH + 2 * nS + 2 * nQ) x = wo4[j - 3 * nH - 2 * nS - nQ];
        else return;
    }
    __half h[4];
    h[0] = __float2half(x.x); h[1] = __float2half(x.y);
    h[2] = __float2half(x.z); h[3] = __float2half(x.w);
    *(uint2*)(dst + 4 * (size_t)di) = *(uint2*)h;
}

// ---------------- fused gate (vec x4, fast math, fp16 R input) ----------------
__global__ void gate_kernel(const float* __restrict__ prev_y,
                            const float* __restrict__ prev_hidden,
                            const float* __restrict__ coarse,
                            const float* __restrict__ W_Ic,
                            const float* __restrict__ W_If,
                            const float* __restrict__ bias_u,
                            const float* __restrict__ bias_r,
                            const float* __restrict__ bias_e,
                            const __half* __restrict__ Rbuf,
                            float* __restrict__ hidden_out,
                            __half* __restrict__ hid_h)
{
    const int HV = H_ / 4;
    int v = blockIdx.x * blockDim.x + threadIdx.x;
    if (v >= B_ * HV) return;
    int b = v / HV;
    int j = (v - b * HV) * 4;
    size_t idx = (size_t)b * H_ + j;
    const size_t NBH = (size_t)B_ * H_;

    float py0 = prev_y[2 * b], py1 = prev_y[2 * b + 1];

    __half Ru2[4], Rr2[4], Re2[4];
    *(uint2*)Ru2 = *(const uint2*)(Rbuf + idx);
    *(uint2*)Rr2 = *(const uint2*)(Rbuf + NBH + idx);
    *(uint2*)Re2 = *(const uint2*)(Rbuf + 2 * NBH + idx);
    float4 ph4 = *(const float4*)(prev_hidden + idx);
    const float* ph = (const float*)&ph4;

    float h[4];
    if (j < S_) {
#pragma unroll
        for (int q = 0; q < 4; ++q) {
            int jj = j + q;
            float Iu = py0 * W_Ic[jj * 2] + py1 * W_Ic[jj * 2 + 1];
            float Ir = py0 * W_Ic[(S_ + jj) * 2] + py1 * W_Ic[(S_ + jj) * 2 + 1];
            float Ie = py0 * W_Ic[(2 * S_ + jj) * 2] + py1 * W_Ic[(2 * S_ + jj) * 2 + 1];
            float u = fsigm(__half2float(Ru2[q]) + Iu + bias_u[jj]);
            float r = fsigm(__half2float(Rr2[q]) + Ir + bias_r[jj]);
            float e = ftanh(r * __half2float(Re2[q]) + Ie + bias_e[jj]);
            h[q] = u * ph[q] + (1.f - u) * e;
        }
    } else {
        float cc = coarse[b];
#pragma unroll
        for (int q = 0; q < 4; ++q) {
            int jj = j + q;
            int jf = jj - S_;
            float Iu = py0 * W_If[jf * 3] + py1 * W_If[jf * 3 + 1] + cc * W_If[jf * 3 + 2];
            float Ir = py0 * W_If[(S_ + jf) * 3] + py1 * W_If[(S_ + jf) * 3 + 1] + cc * W_If[(S_ + jf) * 3 + 2];
            float Ie = py0 * W_If[(2 * S_ + jf) * 3] + py1 * W_If[(2 * S_ + jf) * 3 + 1] + cc * W_If[(2 * S_ + jf) * 3 + 2];
            float u = fsigm(__half2float(Ru2[q]) + Iu + bias_u[jj]);
            float r = fsigm(__half2float(Rr2[q]) + Ir + bias_r[jj]);
            float e = ftanh(r * __half2float(Re2[q]) + Ie + bias_e[jj]);
            h[q] = u * ph[q] + (1.f - u) * e;
        }
    }

    *(float4*)(hidden_out + idx) = make_float4(h[0], h[1], h[2], h[3]);

    __half hh[4];
#pragma unroll
    for (int q = 0; q < 4; ++q) hh[q] = __float2half(h[q]);
    *(uint2*)(hid_h + idx) = *(uint2*)hh;
}

// ---------------- launch ----------------
extern "C" void kernel_launch(void* const* d_in, const int* in_sizes, int n_in,
                              void* d_out, int out_size)
{
    const float* prev_y      = (const float*)d_in[0];
    const float* prev_hidden = (const float*)d_in[1];
    const float* coarse      = (const float*)d_in[2];
    const float* W_Ru        = (const float*)d_in[3];
    const float* W_Rr        = (const float*)d_in[4];
    const float* W_Re        = (const float*)d_in[5];
    const float* W_Ic        = (const float*)d_in[6];
    const float* W_If        = (const float*)d_in[7];
    const float* W_O1        = (const float*)d_in[8];
    const float* b_O1        = (const float*)d_in[9];
    const float* W_O2        = (const float*)d_in[10];
    const float* b_O2        = (const float*)d_in[11];
    const float* W_O3        = (const float*)d_in[12];
    const float* b_O3        = (const float*)d_in[13];
    const float* W_O4        = (const float*)d_in[14];
    const float* b_O4        = (const float*)d_in[15];
    const float* bias_u      = (const float*)d_in[16];
    const float* bias_r      = (const float*)d_in[17];
    const float* bias_e      = (const float*)d_in[18];

    float* out        = (float*)d_out;
    float* out_coarse = out;
    float* hidden     = out + 2 * (size_t)B_ * Q_;

    __half *Rbuf, *Ah, *Hh, *Th, *Wh;
    cudaGetSymbolAddress((void**)&Rbuf, g_R);
    cudaGetSymbolAddress((void**)&Ah, g_Ah);
    cudaGetSymbolAddress((void**)&Hh, g_Hh);
    cudaGetSymbolAddress((void**)&Th, g_Th);
    cudaGetSymbolAddress((void**)&Wh, g_Wh);

    cudaFuncSetAttribute(gemm_mma<0, true>,  cudaFuncAttributeMaxDynamicSharedMemorySize, SMEM_TOTAL);
    cudaFuncSetAttribute(gemm_mma<2, false>, cudaFuncAttributeMaxDynamicSharedMemorySize, SMEM_TOTAL);
    cudaFuncSetAttribute(gemm_mma<1, false>, cudaFuncAttributeMaxDynamicSharedMemorySize, SMEM_TOTAL);

    const int NBS = B_ * S_;
    const int NCVT = B_ * H_ / 4 + WSZ / 4;

    // merged converts (1 launch)
    cvtAll_kernel<<<(NCVT + 255) / 256, 256>>>(
        (const float4*)prev_hidden,
        (const float4*)W_Ru, (const float4*)W_Rr, (const float4*)W_Re,
        (const float4*)W_O1, (const float4*)W_O3, (const float4*)W_O2, (const float4*)W_O4,
        Ah, Wh);

    dim3 blk(256);

    // fused recurrent projections -> R (fp16), N = 3*H = 2688
    dim3 g1(3 * H_ / 128, B_ / 128, 1);  // (21, 64)
    gemm_mma<0, true><<<g1, blk, SMEM_TOTAL>>>(Ah, H_, Wh + OFF_WR,
                                               3 * H_, H_, nullptr, nullptr,
                                               nullptr, Rbuf, H_, 0, 0, 0);

    // fused gates -> hidden (fp32 to d_out) + fp16 copy
    gate_kernel<<<(B_ * (H_ / 4) + 255) / 256, 256>>>(prev_y, prev_hidden, coarse, W_Ic, W_If,
                                                      bias_u, bias_r, bias_e, Rbuf, hidden, Hh);

    // relu(h_half @ W^T + b) -> fp16 scratch; z batches O1 / O3
    dim3 g2((S_ + 127) / 128, B_ / 128, 2);  // (4, 64, 2)
    gemm_mma<2, false><<<g2, blk, SMEM_TOTAL>>>(Hh, H_, Wh + OFF_WO1,
                                                S_, S_, b_O1, b_O3,
                                                nullptr, Th, S_,
                                                S_, S_ * S_, NBS);

    // logits -> d_out; z batches O2 / O4
    dim3 g3(Q_ / 128, B_ / 128, 2);  // (2, 64, 2)
    gemm_mma<1, false><<<g3, blk, SMEM_TOTAL>>>(Th, S_, Wh + OFF_WO2,
                                                Q_, S_, b_O2, b_O4,
                                                out_coarse, nullptr, Q_,
                                                NBS, Q_ * S_, B_ * Q_);
}